// round 14
// baseline (speedup 1.0000x reference)
#include <cuda_runtime.h>

#define NN     10000
#define EE     320000
#define FINN   5
#define FOUT   64
#define MLPH   32
#define CC     27
#define HIDD   450
#define FINAL  128
#define MLP_H  32
#define SDIM   168          // 160 (j*5+i) + 5 (x-sum for b2 term) + pad
#define VLEN   (NN*CC)      // 270000
#define MAXL   8            // max edges per lane in GAT reg cache (deg <= 256)

// ---------------- scratch (no allocations allowed) ----------------
// Self-cleaning invariant: every buffer that must be zero at entry is
// zero-initialized at module load AND re-zeroed by the kernel that last
// consumes it, so every graph replay sees identical state.
static __device__ int    g_deg[NN];        // zeroed by k_scan after consumption
static __device__ int    g_off[NN + 1];
static __device__ int    g_rank[EE];
static __device__ float4 g_edata[2 * EE];  // dst-sorted: {x0..x3},{x4,ea0,ea1,src}
static __device__ float4 g_x8[2 * NN];     // x padded to 8 floats (2x float4)
static __device__ float  g_S[NN * SDIM];
static __device__ float  g_xl[NN * CC];
static __device__ float  g_asrc[NN];
static __device__ float  g_adst[NN];
static __device__ int    g_nnz;            // zeroed by last fc2 block
static __device__ int    g_cidx[VLEN];
static __device__ float  g_cval[VLEN];
static __device__ float  g_hid[HIDD];      // zeroed by k_fc2 after consumption
static __device__ float  g_fin[FINAL];     // zeroed (atomicExch) by last fc2 block
static __device__ int    g_done;           // fc2 completion counter; self-cleaned

// ---------------- hist (+ x padding piggybacked on first NN threads) ----------------
__global__ void k_hist(const int* __restrict__ ei, const float* __restrict__ x) {
    int e = blockIdx.x * blockDim.x + threadIdx.x;
    if (e < NN) {
        const float* xp = x + e * FINN;
        g_x8[2 * e]     = make_float4(__ldg(xp), __ldg(xp + 1), __ldg(xp + 2), __ldg(xp + 3));
        g_x8[2 * e + 1] = make_float4(__ldg(xp + 4), 0.f, 0.f, 0.f);
    }
    if (e < EE) g_rank[e] = atomicAdd(&g_deg[ei[EE + e]], 1);
}

// scan via smem: coalesced global in/out; self-cleans g_deg
__global__ void k_scan() {
    __shared__ int sdeg[10240];
    __shared__ int wsum[8];
    __shared__ int woff[8];
    int tid = threadIdx.x;
    for (int i = tid; i < 10240; i += 256) sdeg[i] = (i < NN) ? g_deg[i] : 0;
    __syncthreads();
    int start = tid * 40;
    int local = 0;
#pragma unroll 8
    for (int i = 0; i < 40; i++) local += sdeg[start + i];
    int lane = tid & 31, w = tid >> 5;
    int incl = local;
    for (int s = 1; s < 32; s <<= 1) {
        int t = __shfl_up_sync(0xffffffffu, incl, s);
        if (lane >= s) incl += t;
    }
    if (lane == 31) wsum[w] = incl;
    __syncthreads();
    if (tid == 0) {
        int c = 0;
        for (int i = 0; i < 8; i++) { woff[i] = c; c += wsum[i]; }
    }
    __syncthreads();
    int run = incl - local + woff[w];
#pragma unroll 8
    for (int i = 0; i < 40; i++) {
        int t = sdeg[start + i];
        sdeg[start + i] = run;
        run += t;
    }
    __syncthreads();
    for (int i = tid; i < NN; i += 256) {
        g_off[i] = sdeg[i];
        g_deg[i] = 0;                      // restore zero-state for next run
    }
    if (tid == 0) g_off[NN] = EE;
}

// atomic-free scatter: build full dst-sorted 32B edge records
__global__ void k_scatter(const int* __restrict__ ei, const float* __restrict__ ea) {
    int e = blockIdx.x * blockDim.x + threadIdx.x;
    if (e >= EE) return;
    int dst = __ldg(&ei[EE + e]);
    int src = __ldg(&ei[e]);
    float2 eav = __ldg((const float2*)ea + e);
    int slot = g_off[dst] + g_rank[e];
    float4 xa = __ldg(&g_x8[2 * src]);
    float4 xb = __ldg(&g_x8[2 * src + 1]);
    g_edata[2 * slot]     = xa;
    g_edata[2 * slot + 1] = make_float4(xb.x, eav.x, eav.y, __int_as_float(src));
}

// ---------------- S build: warp per node, lane = j; pure streaming ----------------
__global__ void k_S(const float* __restrict__ w1, const float* __restrict__ b1) {
    __shared__ float w1s[2 * MLP_H];
    __shared__ float b1s[MLP_H];
    int tid = threadIdx.x;
    if (tid < 2 * MLP_H) w1s[tid] = w1[tid];
    if (tid < MLP_H)     b1s[tid] = b1[tid];
    __syncthreads();

    int n = blockIdx.x * 8 + (tid >> 5);
    if (n >= NN) return;
    int j = tid & 31;
    float wa = w1s[j], wb = w1s[MLP_H + j], bb = b1s[j];

    float s0 = 0.f, s1 = 0.f, s2 = 0.f, s3 = 0.f, s4 = 0.f, xs = 0.f;
    int k0 = g_off[n], k1 = g_off[n + 1];
    const float4* ep   = g_edata + 2 * k0;
    const float4* eend = g_edata + 2 * k1;
    // 2-edge batch: 4 independent LDG.128 w/ immediate offsets, then pure FMA
    for (; ep + 4 <= eend; ep += 4) {
        float4 A0 = __ldg(ep);
        float4 B0 = __ldg(ep + 1);
        float4 A1 = __ldg(ep + 2);
        float4 B1 = __ldg(ep + 3);
        float h0 = fmaxf(fmaf(B0.y, wa, fmaf(B0.z, wb, bb)), 0.f);
        float h1 = fmaxf(fmaf(B1.y, wa, fmaf(B1.z, wb, bb)), 0.f);
        s0 = fmaf(h0, A0.x, s0); s1 = fmaf(h0, A0.y, s1); s2 = fmaf(h0, A0.z, s2);
        s3 = fmaf(h0, A0.w, s3); s4 = fmaf(h0, B0.x, s4);
        s0 = fmaf(h1, A1.x, s0); s1 = fmaf(h1, A1.y, s1); s2 = fmaf(h1, A1.z, s2);
        s3 = fmaf(h1, A1.w, s3); s4 = fmaf(h1, B1.x, s4);
        if (j < FINN) {
            float v0 = (j == 0) ? A0.x : (j == 1) ? A0.y : (j == 2) ? A0.z : (j == 3) ? A0.w : B0.x;
            float v1 = (j == 0) ? A1.x : (j == 1) ? A1.y : (j == 2) ? A1.z : (j == 3) ? A1.w : B1.x;
            xs += v0 + v1;
        }
    }
    if (ep < eend) {
        float4 A0 = __ldg(ep);
        float4 B0 = __ldg(ep + 1);
        float h0 = fmaxf(fmaf(B0.y, wa, fmaf(B0.z, wb, bb)), 0.f);
        s0 = fmaf(h0, A0.x, s0); s1 = fmaf(h0, A0.y, s1); s2 = fmaf(h0, A0.z, s2);
        s3 = fmaf(h0, A0.w, s3); s4 = fmaf(h0, B0.x, s4);
        if (j < FINN) {
            float v0 = (j == 0) ? A0.x : (j == 1) ? A0.y : (j == 2) ? A0.z : (j == 3) ? A0.w : B0.x;
            xs += v0;
        }
    }
    float* Sp = g_S + n * SDIM + j * 5;
    Sp[0] = s0; Sp[1] = s1; Sp[2] = s2; Sp[3] = s3; Sp[4] = s4;
    if (j < FINN) g_S[n * SDIM + 160 + j] = xs;
}

// ---------------- fused: x1 = relu(NNConv), xl = x1@gat_w, a_src/a_dst ----------------
__global__ void k_x1xl(const float* __restrict__ x, const float* __restrict__ w2,
                       const float* __restrict__ b2, const float* __restrict__ root,
                       const float* __restrict__ nbias, const float* __restrict__ gw,
                       const float* __restrict__ asv, const float* __restrict__ adv) {
    __shared__ float x1s[8][64];
    int w = threadIdx.x >> 5, lane = threadIdx.x & 31;
    int n = blockIdx.x * 8 + w;
    if (n >= NN) return;
    const float* Sp = g_S + n * SDIM;
    int o0 = lane, o1 = lane + 32;

    float acc0 = __ldg(&nbias[o0]);
    float acc1 = __ldg(&nbias[o1]);
    const float* xp = x + n * FINN;
#pragma unroll
    for (int i = 0; i < FINN; i++) {
        float xi = __ldg(xp + i);
        acc0 = fmaf(xi, __ldg(&root[i * FOUT + o0]), acc0);
        acc1 = fmaf(xi, __ldg(&root[i * FOUT + o1]), acc1);
    }
#pragma unroll 4
    for (int j = 0; j < MLP_H; j++) {
#pragma unroll
        for (int i = 0; i < FINN; i++) {
            float sv = Sp[j * 5 + i];
            acc0 = fmaf(sv, __ldg(&w2[j * 320 + i * 64 + o0]), acc0);
            acc1 = fmaf(sv, __ldg(&w2[j * 320 + i * 64 + o1]), acc1);
        }
    }
#pragma unroll
    for (int i = 0; i < FINN; i++) {
        float sv = Sp[160 + i];
        acc0 = fmaf(sv, __ldg(&b2[i * 64 + o0]), acc0);
        acc1 = fmaf(sv, __ldg(&b2[i * 64 + o1]), acc1);
    }
    x1s[w][o0] = fmaxf(acc0, 0.f);
    x1s[w][o1] = fmaxf(acc1, 0.f);
    __syncwarp();

    int c = lane;
    float acc = 0.f;
    if (c < CC) {
#pragma unroll 8
        for (int o = 0; o < FOUT; o++)
            acc = fmaf(x1s[w][o], __ldg(&gw[o * CC + c]), acc);
        g_xl[n * CC + c] = acc;
    }
    float vs = (c < CC) ? acc * __ldg(&asv[c]) : 0.f;
    float vd = (c < CC) ? acc * __ldg(&adv[c]) : 0.f;
    for (int s = 16; s; s >>= 1) {
        vs += __shfl_xor_sync(0xffffffffu, vs, s);
        vd += __shfl_xor_sync(0xffffffffu, vd, s);
    }
    if (lane == 0) { g_asrc[n] = vs; g_adst[n] = vd; }
}

__device__ __forceinline__ float lrelu(float a) { return a > 0.f ? a : 0.2f * a; }

// ---------------- GAT: online softmax + reg-cached edges + fused compaction ----------------
__global__ void k_gat(const float* __restrict__ gbias) {
    int n = blockIdx.x * 8 + (threadIdx.x >> 5);
    if (n >= NN) return;
    int lane = threadIdx.x & 31;
    int k0 = g_off[n], k1 = g_off[n + 1];
    int deg = k1 - k0;
    float ad = g_adst[n];
    float aself = lrelu(g_asrc[n] + ad);

    float sa[MAXL]; int ss[MAXL];
    int nl = 0;
    float m = -1e30f, d = 0.f;
    for (int k = k0 + lane; k < k1; k += 32) {
        int s = __float_as_int(__ldg(&g_edata[2 * k + 1]).w);
        float a = lrelu(__ldg(&g_asrc[s]) + ad);
        if (nl < MAXL) { sa[nl] = a; ss[nl] = s; }
        nl++;
        float mn = fmaxf(m, a);
        d = fmaf(d, __expf(m - mn), __expf(a - mn));
        m = mn;
    }
    for (int s = 16; s; s >>= 1) {
        float m2 = __shfl_xor_sync(0xffffffffu, m, s);
        float d2 = __shfl_xor_sync(0xffffffffu, d, s);
        float mn = fmaxf(m, m2);
        d = fmaf(d, __expf(m - mn), d2 * __expf(m2 - mn));
        m = mn;
    }
    {
        float mn = fmaxf(m, aself);
        d = fmaf(d, __expf(m - mn), __expf(aself - mn));
        m = mn;
    }
    float inv = 1.f / d;

    int c = lane;
    float out = (c < CC) ? __expf(aself - m) * inv * g_xl[n * CC + c] : 0.f;

    if (deg <= 32 * MAXL) {
        int nb = (deg + 31) >> 5;
        for (int q = 0; q < nb; q++) {
            float wq = (q < nl) ? __expf(sa[q] - m) * inv : 0.f;
            int sq = (q < nl) ? ss[q] : 0;
            int cnt = min(32, deg - (q << 5));
            for (int i = 0; i < cnt; i++) {
                float wi = __shfl_sync(0xffffffffu, wq, i);
                int si = __shfl_sync(0xffffffffu, sq, i);
                if (c < CC) out = fmaf(wi, __ldg(&g_xl[si * CC + c]), out);
            }
        }
    } else {
        for (int k = k0; k < k1; k++) {
            int s2 = __float_as_int(__ldg(&g_edata[2 * k + 1]).w);
            float wv = __expf(lrelu(__ldg(&g_asrc[s2]) + ad) - m) * inv;
            if (c < CC) out = fmaf(wv, __ldg(&g_xl[s2 * CC + c]), out);
        }
    }

    float r = 0.f;
    bool pred = false;
    if (c < CC) {
        r = out + __ldg(&gbias[c]);
        pred = (r > 0.f);
    }
    unsigned mask = __ballot_sync(0xffffffffu, pred);
    int cnt = __popc(mask);
    if (cnt) {
        int leader = __ffs(mask) - 1;
        int base = 0;
        if (lane == leader) base = atomicAdd(&g_nnz, cnt);
        base = __shfl_sync(0xffffffffu, base, leader);
        if (pred) {
            int off = __popc(mask & ((1u << lane) - 1));
            g_cidx[base + off] = n * CC + c;
            g_cval[base + off] = r;
        }
    }
}

// ---------------- fc1: compacted-row GEMV, explicit 8-row batch ----------------
__global__ void k_fc1(const float* __restrict__ w) {
    int nnz = g_nnz;
    int per = (nnz + gridDim.x - 1) / gridDim.x;
    int i0 = blockIdx.x * per;
    int i1 = i0 + per; if (i1 > nnz) i1 = nnz;
    int t = threadIdx.x;
    float a0 = 0.f, a1 = 0.f;
    int i = i0;
    for (; i + 8 <= i1; i += 8) {
        int r0 = __ldg(&g_cidx[i]),     r1 = __ldg(&g_cidx[i + 1]);
        int r2 = __ldg(&g_cidx[i + 2]), r3 = __ldg(&g_cidx[i + 3]);
        int r4 = __ldg(&g_cidx[i + 4]), r5 = __ldg(&g_cidx[i + 5]);
        int r6 = __ldg(&g_cidx[i + 6]), r7 = __ldg(&g_cidx[i + 7]);
        float v0 = __ldg(&g_cval[i]),     v1 = __ldg(&g_cval[i + 1]);
        float v2 = __ldg(&g_cval[i + 2]), v3 = __ldg(&g_cval[i + 3]);
        float v4 = __ldg(&g_cval[i + 4]), v5 = __ldg(&g_cval[i + 5]);
        float v6 = __ldg(&g_cval[i + 6]), v7 = __ldg(&g_cval[i + 7]);
        const float* p0 = w + (size_t)r0 * HIDD;
        const float* p1 = w + (size_t)r1 * HIDD;
        const float* p2 = w + (size_t)r2 * HIDD;
        const float* p3 = w + (size_t)r3 * HIDD;
        const float* p4 = w + (size_t)r4 * HIDD;
        const float* p5 = w + (size_t)r5 * HIDD;
        const float* p6 = w + (size_t)r6 * HIDD;
        const float* p7 = w + (size_t)r7 * HIDD;
        a0 = fmaf(v0, __ldg(p0 + t), a0);
        a0 = fmaf(v1, __ldg(p1 + t), a0);
        a0 = fmaf(v2, __ldg(p2 + t), a0);
        a0 = fmaf(v3, __ldg(p3 + t), a0);
        a0 = fmaf(v4, __ldg(p4 + t), a0);
        a0 = fmaf(v5, __ldg(p5 + t), a0);
        a0 = fmaf(v6, __ldg(p6 + t), a0);
        a0 = fmaf(v7, __ldg(p7 + t), a0);
        if (t < HIDD - 256) {
            a1 = fmaf(v0, __ldg(p0 + 256 + t), a1);
            a1 = fmaf(v1, __ldg(p1 + 256 + t), a1);
            a1 = fmaf(v2, __ldg(p2 + 256 + t), a1);
            a1 = fmaf(v3, __ldg(p3 + 256 + t), a1);
            a1 = fmaf(v4, __ldg(p4 + 256 + t), a1);
            a1 = fmaf(v5, __ldg(p5 + 256 + t), a1);
            a1 = fmaf(v6, __ldg(p6 + 256 + t), a1);
            a1 = fmaf(v7, __ldg(p7 + 256 + t), a1);
        }
    }
    for (; i < i1; i++) {
        int r = __ldg(&g_cidx[i]);
        float v = __ldg(&g_cval[i]);
        const float* p = w + (size_t)r * HIDD;
        a0 = fmaf(v, __ldg(p + t), a0);
        if (t < HIDD - 256) a1 = fmaf(v, __ldg(p + 256 + t), a1);
    }
    atomicAdd(&g_hid[t], a0);
    if (t < HIDD - 256) atomicAdd(&g_hid[256 + t], a1);
}

// ---------------- fc2 + final output (last-block pattern); self-cleans ----------------
__global__ void k_fc2(const float* __restrict__ b1v, const float* __restrict__ w2,
                      const float* __restrict__ b2v, float* __restrict__ out) {
    __shared__ float hs[15];
    __shared__ int lastFlag;
    int b = blockIdx.x;
    int t = threadIdx.x;
    if (t < 15) {
        int h = b * 15 + t;
        float hv = g_hid[h] + __ldg(&b1v[h]);
        hs[t] = hv > 0.f ? hv : 0.f;
        g_hid[h] = 0.f;                    // restore zero-state
    }
    __syncthreads();
    float acc = 0.f;
#pragma unroll
    for (int i = 0; i < 15; i++) {
        int h = b * 15 + i;
        acc = fmaf(hs[i], __ldg(&w2[h * FINAL + t]), acc);
    }
    atomicAdd(&g_fin[t], acc);
    __threadfence();
    __syncthreads();                       // block's atomics + fence complete
    if (t == 0) lastFlag = (atomicAdd(&g_done, 1) == 29);
    __syncthreads();
    if (lastFlag) {
        // all 30 blocks' g_fin contributions are visible (fence + counter)
        float v = atomicExch(&g_fin[t], 0.f) + __ldg(&b2v[t]);  // read + self-clean
        out[t] = v > 0.f ? v : 0.f;
        if (t == 0) { g_done = 0; g_nnz = 0; }
    }
}

// ---------------- launcher ----------------
extern "C" void kernel_launch(void* const* d_in, const int* in_sizes, int n_in,
                              void* d_out, int out_size) {
    const float* x        = (const float*)d_in[0];
    const int*   ei       = (const int*)  d_in[1];
    const float* ea       = (const float*)d_in[2];
    const float* mlp_w1   = (const float*)d_in[3];
    const float* mlp_b1   = (const float*)d_in[4];
    const float* mlp_w2   = (const float*)d_in[5];
    const float* mlp_b2   = (const float*)d_in[6];
    const float* nn_root  = (const float*)d_in[7];
    const float* nn_bias  = (const float*)d_in[8];
    const float* gat_w    = (const float*)d_in[9];
    const float* att_src  = (const float*)d_in[10];
    const float* att_dst  = (const float*)d_in[11];
    const float* gat_bias = (const float*)d_in[12];
    const float* fc1_w    = (const float*)d_in[13];
    const float* fc1_b    = (const float*)d_in[14];
    const float* fc2_w    = (const float*)d_in[15];
    const float* fc2_b    = (const float*)d_in[16];
    float* out = (float*)d_out;

    k_hist<<<(EE + 255) / 256, 256>>>(ei, x);
    k_scan<<<1, 256>>>();
    k_scatter<<<(EE + 255) / 256, 256>>>(ei, ea);
    k_S<<<(NN + 7) / 8, 256>>>(mlp_w1, mlp_b1);
    k_x1xl<<<(NN + 7) / 8, 256>>>(x, mlp_w2, mlp_b2, nn_root, nn_bias,
                                  gat_w, att_src, att_dst);
    k_gat<<<(NN + 7) / 8, 256>>>(gat_bias);
    k_fc1<<<2048, 256>>>(fc1_w);
    k_fc2<<<30, 128>>>(fc1_b, fc2_w, fc2_b, out);
}

// round 15
// speedup vs baseline: 1.0331x; 1.0331x over previous
#include <cuda_runtime.h>

#define NN     10000
#define EE     320000
#define FINN   5
#define FOUT   64
#define MLPH   32
#define CC     27
#define HIDD   450
#define FINAL  128
#define MLP_H  32
#define SDIM   168          // 160 (j*5+i) + 5 (x-sum for b2 term) + pad
#define VLEN   (NN*CC)      // 270000
#define MAXL   8            // max edges per lane in GAT reg cache (deg <= 256)

// ---------------- scratch (no allocations allowed) ----------------
// Self-cleaning invariant: zero-state restored by the last consumer.
static __device__ int    g_deg[NN];        // zeroed by k_scan
static __device__ int    g_off[NN + 1];
static __device__ int    g_rank[EE];
static __device__ int    g_esrc[EE];       // dst-sorted source ids
static __device__ float2 g_eea[EE];        // dst-sorted edge attrs
static __device__ float4 g_x8[2 * NN];     // x padded to 8 floats (2x float4)
static __device__ float  g_S[NN * SDIM];
static __device__ float  g_xl[NN * CC];
static __device__ float  g_asrc[NN];
static __device__ float  g_adst[NN];
static __device__ int    g_nnz;            // zeroed by k_out
static __device__ int    g_cidx[VLEN];
static __device__ float  g_cval[VLEN];
static __device__ float  g_hid[HIDD];      // zeroed by k_fc2
static __device__ float  g_fin[FINAL];     // zeroed by k_out

// ---------------- hist (+ x padding piggybacked on first NN threads) ----------------
__global__ void k_hist(const int* __restrict__ ei, const float* __restrict__ x) {
    int e = blockIdx.x * blockDim.x + threadIdx.x;
    if (e < NN) {
        const float* xp = x + e * FINN;
        g_x8[2 * e]     = make_float4(__ldg(xp), __ldg(xp + 1), __ldg(xp + 2), __ldg(xp + 3));
        g_x8[2 * e + 1] = make_float4(__ldg(xp + 4), 0.f, 0.f, 0.f);
    }
    if (e < EE) g_rank[e] = atomicAdd(&g_deg[ei[EE + e]], 1);
}

// scan via smem: coalesced global in/out; self-cleans g_deg
__global__ void k_scan() {
    __shared__ int sdeg[10240];
    __shared__ int wsum[8];
    __shared__ int woff[8];
    int tid = threadIdx.x;
    for (int i = tid; i < 10240; i += 256) sdeg[i] = (i < NN) ? g_deg[i] : 0;
    __syncthreads();
    int start = tid * 40;
    int local = 0;
#pragma unroll 8
    for (int i = 0; i < 40; i++) local += sdeg[start + i];
    int lane = tid & 31, w = tid >> 5;
    int incl = local;
    for (int s = 1; s < 32; s <<= 1) {
        int t = __shfl_up_sync(0xffffffffu, incl, s);
        if (lane >= s) incl += t;
    }
    if (lane == 31) wsum[w] = incl;
    __syncthreads();
    if (tid == 0) {
        int c = 0;
        for (int i = 0; i < 8; i++) { woff[i] = c; c += wsum[i]; }
    }
    __syncthreads();
    int run = incl - local + woff[w];
#pragma unroll 8
    for (int i = 0; i < 40; i++) {
        int t = sdeg[start + i];
        sdeg[start + i] = run;
        run += t;
    }
    __syncthreads();
    for (int i = tid; i < NN; i += 256) {
        g_off[i] = sdeg[i];
        g_deg[i] = 0;
    }
    if (tid == 0) g_off[NN] = EE;
}

// atomic-free scatter: dst-sorted (src, edge_attr) streams (12 B/edge)
__global__ void k_scatter(const int* __restrict__ ei, const float* __restrict__ ea) {
    int e = blockIdx.x * blockDim.x + threadIdx.x;
    if (e >= EE) return;
    int dst = __ldg(&ei[EE + e]);
    int slot = g_off[dst] + g_rank[e];
    g_esrc[slot] = __ldg(&ei[e]);
    g_eea[slot] = __ldg((const float2*)ea + e);
}

// ---------------- S build: TWO warps per node (halved serial depth) ----------------
// Warp pair (p=0,1) splits the node's edge range in half; each runs the
// 2-edge-batched accumulation; p=0 spills partials to smem; p=1 combines.
__global__ void k_S(const float* __restrict__ w1, const float* __restrict__ b1) {
    __shared__ float w1s[2 * MLP_H];
    __shared__ float b1s[MLP_H];
    __shared__ float part[4][168];         // p=0 partials: 160 S + 5 xs
    int tid = threadIdx.x;
    if (tid < 2 * MLP_H) w1s[tid] = w1[tid];
    if (tid < MLP_H)     b1s[tid] = b1[tid];
    __syncthreads();

    int wid = tid >> 5;
    int slot = wid >> 1;                   // 0..3: node slot within block
    int p = wid & 1;                       // warp parity within the pair
    int n = blockIdx.x * 4 + slot;
    int j = tid & 31;
    float wa = w1s[j], wb = w1s[MLP_H + j], bb = b1s[j];

    float s0 = 0.f, s1 = 0.f, s2 = 0.f, s3 = 0.f, s4 = 0.f, xs = 0.f;
    if (n < NN) {
        int k0 = g_off[n], k1 = g_off[n + 1];
        int deg = k1 - k0;
        int half = (deg + 1) >> 1;
        int a0 = k0 + p * half;
        int a1 = a0 + half; if (a1 > k1) a1 = k1;
        int k = a0;
        for (; k + 2 <= a1; k += 2) {
            int sa = __ldg(&g_esrc[k]);
            int sb = __ldg(&g_esrc[k + 1]);
            float2 ea0 = __ldg(&g_eea[k]);
            float2 ea1 = __ldg(&g_eea[k + 1]);
            float4 xa0 = __ldg(&g_x8[2 * sa]);
            float4 xb0 = __ldg(&g_x8[2 * sa + 1]);
            float4 xa1 = __ldg(&g_x8[2 * sb]);
            float4 xb1 = __ldg(&g_x8[2 * sb + 1]);
            float h0 = fmaxf(fmaf(ea0.x, wa, fmaf(ea0.y, wb, bb)), 0.f);
            float h1 = fmaxf(fmaf(ea1.x, wa, fmaf(ea1.y, wb, bb)), 0.f);
            s0 = fmaf(h0, xa0.x, s0); s1 = fmaf(h0, xa0.y, s1); s2 = fmaf(h0, xa0.z, s2);
            s3 = fmaf(h0, xa0.w, s3); s4 = fmaf(h0, xb0.x, s4);
            s0 = fmaf(h1, xa1.x, s0); s1 = fmaf(h1, xa1.y, s1); s2 = fmaf(h1, xa1.z, s2);
            s3 = fmaf(h1, xa1.w, s3); s4 = fmaf(h1, xb1.x, s4);
            if (j < FINN) {
                float v0 = (j == 0) ? xa0.x : (j == 1) ? xa0.y : (j == 2) ? xa0.z : (j == 3) ? xa0.w : xb0.x;
                float v1 = (j == 0) ? xa1.x : (j == 1) ? xa1.y : (j == 2) ? xa1.z : (j == 3) ? xa1.w : xb1.x;
                xs += v0 + v1;
            }
        }
        if (k < a1) {
            int sa = __ldg(&g_esrc[k]);
            float2 ea0 = __ldg(&g_eea[k]);
            float4 xa0 = __ldg(&g_x8[2 * sa]);
            float4 xb0 = __ldg(&g_x8[2 * sa + 1]);
            float h0 = fmaxf(fmaf(ea0.x, wa, fmaf(ea0.y, wb, bb)), 0.f);
            s0 = fmaf(h0, xa0.x, s0); s1 = fmaf(h0, xa0.y, s1); s2 = fmaf(h0, xa0.z, s2);
            s3 = fmaf(h0, xa0.w, s3); s4 = fmaf(h0, xb0.x, s4);
            if (j < FINN) {
                float v0 = (j == 0) ? xa0.x : (j == 1) ? xa0.y : (j == 2) ? xa0.z : (j == 3) ? xa0.w : xb0.x;
                xs += v0;
            }
        }
    }

    if (p == 0) {
        float* pp = part[slot] + j * 5;
        pp[0] = s0; pp[1] = s1; pp[2] = s2; pp[3] = s3; pp[4] = s4;
        if (j < FINN) part[slot][160 + j] = xs;
    }
    __syncthreads();
    if (p == 1 && n < NN) {
        const float* pp = part[slot] + j * 5;
        float* Sp = g_S + n * SDIM + j * 5;
        Sp[0] = s0 + pp[0]; Sp[1] = s1 + pp[1]; Sp[2] = s2 + pp[2];
        Sp[3] = s3 + pp[3]; Sp[4] = s4 + pp[4];
        if (j < FINN) g_S[n * SDIM + 160 + j] = xs + part[slot][160 + j];
    }
}

// ---------------- fused: x1 = relu(NNConv), xl = x1@gat_w, a_src/a_dst ----------------
__global__ void k_x1xl(const float* __restrict__ x, const float* __restrict__ w2,
                       const float* __restrict__ b2, const float* __restrict__ root,
                       const float* __restrict__ nbias, const float* __restrict__ gw,
                       const float* __restrict__ asv, const float* __restrict__ adv) {
    __shared__ float x1s[8][64];
    int w = threadIdx.x >> 5, lane = threadIdx.x & 31;
    int n = blockIdx.x * 8 + w;
    if (n >= NN) return;
    const float* Sp = g_S + n * SDIM;
    int o0 = lane, o1 = lane + 32;

    float acc0 = __ldg(&nbias[o0]);
    float acc1 = __ldg(&nbias[o1]);
    const float* xp = x + n * FINN;
#pragma unroll
    for (int i = 0; i < FINN; i++) {
        float xi = __ldg(xp + i);
        acc0 = fmaf(xi, __ldg(&root[i * FOUT + o0]), acc0);
        acc1 = fmaf(xi, __ldg(&root[i * FOUT + o1]), acc1);
    }
#pragma unroll 4
    for (int j = 0; j < MLP_H; j++) {
#pragma unroll
        for (int i = 0; i < FINN; i++) {
            float sv = Sp[j * 5 + i];
            acc0 = fmaf(sv, __ldg(&w2[j * 320 + i * 64 + o0]), acc0);
            acc1 = fmaf(sv, __ldg(&w2[j * 320 + i * 64 + o1]), acc1);
        }
    }
#pragma unroll
    for (int i = 0; i < FINN; i++) {
        float sv = Sp[160 + i];
        acc0 = fmaf(sv, __ldg(&b2[i * 64 + o0]), acc0);
        acc1 = fmaf(sv, __ldg(&b2[i * 64 + o1]), acc1);
    }
    x1s[w][o0] = fmaxf(acc0, 0.f);
    x1s[w][o1] = fmaxf(acc1, 0.f);
    __syncwarp();

    int c = lane;
    float acc = 0.f;
    if (c < CC) {
#pragma unroll 8
        for (int o = 0; o < FOUT; o++)
            acc = fmaf(x1s[w][o], __ldg(&gw[o * CC + c]), acc);
        g_xl[n * CC + c] = acc;
    }
    float vs = (c < CC) ? acc * __ldg(&asv[c]) : 0.f;
    float vd = (c < CC) ? acc * __ldg(&adv[c]) : 0.f;
    for (int s = 16; s; s >>= 1) {
        vs += __shfl_xor_sync(0xffffffffu, vs, s);
        vd += __shfl_xor_sync(0xffffffffu, vd, s);
    }
    if (lane == 0) { g_asrc[n] = vs; g_adst[n] = vd; }
}

__device__ __forceinline__ float lrelu(float a) { return a > 0.f ? a : 0.2f * a; }

// ---------------- GAT: online softmax + reg-cached edges + fused compaction ----------------
__global__ void k_gat(const float* __restrict__ gbias) {
    int n = blockIdx.x * 8 + (threadIdx.x >> 5);
    if (n >= NN) return;
    int lane = threadIdx.x & 31;
    int k0 = g_off[n], k1 = g_off[n + 1];
    int deg = k1 - k0;
    float ad = g_adst[n];
    float aself = lrelu(g_asrc[n] + ad);

    float sa[MAXL]; int ss[MAXL];
    int nl = 0;
    float m = -1e30f, d = 0.f;
    for (int k = k0 + lane; k < k1; k += 32) {
        int s = __ldg(&g_esrc[k]);
        float a = lrelu(__ldg(&g_asrc[s]) + ad);
        if (nl < MAXL) { sa[nl] = a; ss[nl] = s; }
        nl++;
        float mn = fmaxf(m, a);
        d = fmaf(d, __expf(m - mn), __expf(a - mn));
        m = mn;
    }
    for (int s = 16; s; s >>= 1) {
        float m2 = __shfl_xor_sync(0xffffffffu, m, s);
        float d2 = __shfl_xor_sync(0xffffffffu, d, s);
        float mn = fmaxf(m, m2);
        d = fmaf(d, __expf(m - mn), d2 * __expf(m2 - mn));
        m = mn;
    }
    {
        float mn = fmaxf(m, aself);
        d = fmaf(d, __expf(m - mn), __expf(aself - mn));
        m = mn;
    }
    float inv = 1.f / d;

    int c = lane;
    float out = (c < CC) ? __expf(aself - m) * inv * g_xl[n * CC + c] : 0.f;

    if (deg <= 32 * MAXL) {
        int nb = (deg + 31) >> 5;
        for (int q = 0; q < nb; q++) {
            float wq = (q < nl) ? __expf(sa[q] - m) * inv : 0.f;
            int sq = (q < nl) ? ss[q] : 0;
            int cnt = min(32, deg - (q << 5));
            for (int i = 0; i < cnt; i++) {
                float wi = __shfl_sync(0xffffffffu, wq, i);
                int si = __shfl_sync(0xffffffffu, sq, i);
                if (c < CC) out = fmaf(wi, __ldg(&g_xl[si * CC + c]), out);
            }
        }
    } else {
        for (int k = k0; k < k1; k++) {
            int s2 = __ldg(&g_esrc[k]);
            float wv = __expf(lrelu(__ldg(&g_asrc[s2]) + ad) - m) * inv;
            if (c < CC) out = fmaf(wv, __ldg(&g_xl[s2 * CC + c]), out);
        }
    }

    float r = 0.f;
    bool pred = false;
    if (c < CC) {
        r = out + __ldg(&gbias[c]);
        pred = (r > 0.f);
    }
    unsigned mask = __ballot_sync(0xffffffffu, pred);
    int cnt = __popc(mask);
    if (cnt) {
        int leader = __ffs(mask) - 1;
        int base = 0;
        if (lane == leader) base = atomicAdd(&g_nnz, cnt);
        base = __shfl_sync(0xffffffffu, base, leader);
        if (pred) {
            int off = __popc(mask & ((1u << lane) - 1));
            g_cidx[base + off] = n * CC + c;
            g_cval[base + off] = r;
        }
    }
}

// ---------------- fc1: compacted-row GEMV, explicit 8-row batch ----------------
__global__ void k_fc1(const float* __restrict__ w) {
    int nnz = g_nnz;
    int per = (nnz + gridDim.x - 1) / gridDim.x;
    int i0 = blockIdx.x * per;
    int i1 = i0 + per; if (i1 > nnz) i1 = nnz;
    int t = threadIdx.x;
    float a0 = 0.f, a1 = 0.f;
    int i = i0;
    for (; i + 8 <= i1; i += 8) {
        int r0 = __ldg(&g_cidx[i]),     r1 = __ldg(&g_cidx[i + 1]);
        int r2 = __ldg(&g_cidx[i + 2]), r3 = __ldg(&g_cidx[i + 3]);
        int r4 = __ldg(&g_cidx[i + 4]), r5 = __ldg(&g_cidx[i + 5]);
        int r6 = __ldg(&g_cidx[i + 6]), r7 = __ldg(&g_cidx[i + 7]);
        float v0 = __ldg(&g_cval[i]),     v1 = __ldg(&g_cval[i + 1]);
        float v2 = __ldg(&g_cval[i + 2]), v3 = __ldg(&g_cval[i + 3]);
        float v4 = __ldg(&g_cval[i + 4]), v5 = __ldg(&g_cval[i + 5]);
        float v6 = __ldg(&g_cval[i + 6]), v7 = __ldg(&g_cval[i + 7]);
        const float* p0 = w + (size_t)r0 * HIDD;
        const float* p1 = w + (size_t)r1 * HIDD;
        const float* p2 = w + (size_t)r2 * HIDD;
        const float* p3 = w + (size_t)r3 * HIDD;
        const float* p4 = w + (size_t)r4 * HIDD;
        const float* p5 = w + (size_t)r5 * HIDD;
        const float* p6 = w + (size_t)r6 * HIDD;
        const float* p7 = w + (size_t)r7 * HIDD;
        a0 = fmaf(v0, __ldg(p0 + t), a0);
        a0 = fmaf(v1, __ldg(p1 + t), a0);
        a0 = fmaf(v2, __ldg(p2 + t), a0);
        a0 = fmaf(v3, __ldg(p3 + t), a0);
        a0 = fmaf(v4, __ldg(p4 + t), a0);
        a0 = fmaf(v5, __ldg(p5 + t), a0);
        a0 = fmaf(v6, __ldg(p6 + t), a0);
        a0 = fmaf(v7, __ldg(p7 + t), a0);
        if (t < HIDD - 256) {
            a1 = fmaf(v0, __ldg(p0 + 256 + t), a1);
            a1 = fmaf(v1, __ldg(p1 + 256 + t), a1);
            a1 = fmaf(v2, __ldg(p2 + 256 + t), a1);
            a1 = fmaf(v3, __ldg(p3 + 256 + t), a1);
            a1 = fmaf(v4, __ldg(p4 + 256 + t), a1);
            a1 = fmaf(v5, __ldg(p5 + 256 + t), a1);
            a1 = fmaf(v6, __ldg(p6 + 256 + t), a1);
            a1 = fmaf(v7, __ldg(p7 + 256 + t), a1);
        }
    }
    for (; i < i1; i++) {
        int r = __ldg(&g_cidx[i]);
        float v = __ldg(&g_cval[i]);
        const float* p = w + (size_t)r * HIDD;
        a0 = fmaf(v, __ldg(p + t), a0);
        if (t < HIDD - 256) a1 = fmaf(v, __ldg(p + 256 + t), a1);
    }
    atomicAdd(&g_hid[t], a0);
    if (t < HIDD - 256) atomicAdd(&g_hid[256 + t], a1);
}

// ---------------- fc2: 30 blocks x 15 rows, atomic partials; self-cleans g_hid ----------------
__global__ void k_fc2(const float* __restrict__ b1v, const float* __restrict__ w2) {
    __shared__ float hs[15];
    int b = blockIdx.x;
    int t = threadIdx.x;
    if (t < 15) {
        int h = b * 15 + t;
        float hv = g_hid[h] + __ldg(&b1v[h]);
        hs[t] = hv > 0.f ? hv : 0.f;
    }
    __syncthreads();
    float acc = 0.f;
#pragma unroll
    for (int i = 0; i < 15; i++) {
        int h = b * 15 + i;
        acc = fmaf(hs[i], __ldg(&w2[h * FINAL + t]), acc);
    }
    atomicAdd(&g_fin[t], acc);
    if (t < 15) g_hid[b * 15 + t] = 0.f;
}

// ---------------- out: final relu; self-cleans g_fin and g_nnz ----------------
__global__ void k_out(const float* __restrict__ b2v, float* __restrict__ out) {
    int t = threadIdx.x;
    float v = g_fin[t] + __ldg(&b2v[t]);
    g_fin[t] = 0.f;
    if (t == 0) g_nnz = 0;
    out[t] = v > 0.f ? v : 0.f;
}

// ---------------- launcher ----------------
extern "C" void kernel_launch(void* const* d_in, const int* in_sizes, int n_in,
                              void* d_out, int out_size) {
    const float* x        = (const float*)d_in[0];
    const int*   ei       = (const int*)  d_in[1];
    const float* ea       = (const float*)d_in[2];
    const float* mlp_w1   = (const float*)d_in[3];
    const float* mlp_b1   = (const float*)d_in[4];
    const float* mlp_w2   = (const float*)d_in[5];
    const float* mlp_b2   = (const float*)d_in[6];
    const float* nn_root  = (const float*)d_in[7];
    const float* nn_bias  = (const float*)d_in[8];
    const float* gat_w    = (const float*)d_in[9];
    const float* att_src  = (const float*)d_in[10];
    const float* att_dst  = (const float*)d_in[11];
    const float* gat_bias = (const float*)d_in[12];
    const float* fc1_w    = (const float*)d_in[13];
    const float* fc1_b    = (const float*)d_in[14];
    const float* fc2_w    = (const float*)d_in[15];
    const float* fc2_b    = (const float*)d_in[16];
    float* out = (float*)d_out;

    k_hist<<<(EE + 255) / 256, 256>>>(ei, x);
    k_scan<<<1, 256>>>();
    k_scatter<<<(EE + 255) / 256, 256>>>(ei, ea);
    k_S<<<(NN + 3) / 4, 256>>>(mlp_w1, mlp_b1);
    k_x1xl<<<(NN + 7) / 8, 256>>>(x, mlp_w2, mlp_b2, nn_root, nn_bias,
                                  gat_w, att_src, att_dst);
    k_gat<<<(NN + 7) / 8, 256>>>(gat_bias);
    k_fc1<<<2048, 256>>>(fc1_w);
    k_fc2<<<30, 128>>>(fc1_b, fc2_w);
    k_out<<<1, 128>>>(fc2_b, out);
}

// round 16
// speedup vs baseline: 1.1081x; 1.0727x over previous
#include <cuda_runtime.h>

#define NN     10000
#define EE     320000
#define FINN   5
#define FOUT   64
#define MLPH   32
#define CC     27
#define HIDD   450
#define FINAL  128
#define MLP_H  32
#define SDIM   168          // 160 (j*5+i) + 5 (x-sum for b2 term) + pad
#define MAXL   8            // max edges per lane in GAT reg cache (deg <= 256)

// ---------------- scratch (no allocations allowed) ----------------
// Self-cleaning invariant: zero-state restored by the last consumer.
static __device__ int    g_deg[NN];        // zeroed by k_scan
static __device__ int    g_off[NN + 1];
static __device__ int    g_rank[EE];
static __device__ int    g_esrc[EE];       // dst-sorted source ids
static __device__ float2 g_eea[EE];        // dst-sorted edge attrs
static __device__ float4 g_x8[2 * NN];     // x padded to 8 floats (2x float4)
static __device__ float  g_S[NN * SDIM];
static __device__ float  g_xl[NN * CC];
static __device__ float  g_asrc[NN];
static __device__ float  g_adst[NN];
static __device__ float  g_hid[HIDD];      // zeroed by k_fc2
static __device__ float  g_fin[FINAL];     // zeroed by k_out

// ---------------- hist (+ x padding piggybacked on first NN threads) ----------------
__global__ void k_hist(const int* __restrict__ ei, const float* __restrict__ x) {
    int e = blockIdx.x * blockDim.x + threadIdx.x;
    if (e < NN) {
        const float* xp = x + e * FINN;
        g_x8[2 * e]     = make_float4(__ldg(xp), __ldg(xp + 1), __ldg(xp + 2), __ldg(xp + 3));
        g_x8[2 * e + 1] = make_float4(__ldg(xp + 4), 0.f, 0.f, 0.f);
    }
    if (e < EE) g_rank[e] = atomicAdd(&g_deg[ei[EE + e]], 1);
}

// scan via smem: coalesced global in/out; self-cleans g_deg
__global__ void k_scan() {
    __shared__ int sdeg[10240];
    __shared__ int wsum[8];
    __shared__ int woff[8];
    int tid = threadIdx.x;
    for (int i = tid; i < 10240; i += 256) sdeg[i] = (i < NN) ? g_deg[i] : 0;
    __syncthreads();
    int start = tid * 40;
    int local = 0;
#pragma unroll 8
    for (int i = 0; i < 40; i++) local += sdeg[start + i];
    int lane = tid & 31, w = tid >> 5;
    int incl = local;
    for (int s = 1; s < 32; s <<= 1) {
        int t = __shfl_up_sync(0xffffffffu, incl, s);
        if (lane >= s) incl += t;
    }
    if (lane == 31) wsum[w] = incl;
    __syncthreads();
    if (tid == 0) {
        int c = 0;
        for (int i = 0; i < 8; i++) { woff[i] = c; c += wsum[i]; }
    }
    __syncthreads();
    int run = incl - local + woff[w];
#pragma unroll 8
    for (int i = 0; i < 40; i++) {
        int t = sdeg[start + i];
        sdeg[start + i] = run;
        run += t;
    }
    __syncthreads();
    for (int i = tid; i < NN; i += 256) {
        g_off[i] = sdeg[i];
        g_deg[i] = 0;
    }
    if (tid == 0) g_off[NN] = EE;
}

// atomic-free scatter: dst-sorted (src, edge_attr) streams (12 B/edge)
__global__ void k_scatter(const int* __restrict__ ei, const float* __restrict__ ea) {
    int e = blockIdx.x * blockDim.x + threadIdx.x;
    if (e >= EE) return;
    int dst = __ldg(&ei[EE + e]);
    int slot = g_off[dst] + g_rank[e];
    g_esrc[slot] = __ldg(&ei[e]);
    g_eea[slot] = __ldg((const float2*)ea + e);
}

// ---------------- S build: TWO warps per node (halved serial depth) ----------------
__global__ void k_S(const float* __restrict__ w1, const float* __restrict__ b1) {
    __shared__ float w1s[2 * MLP_H];
    __shared__ float b1s[MLP_H];
    __shared__ float part[4][168];
    int tid = threadIdx.x;
    if (tid < 2 * MLP_H) w1s[tid] = w1[tid];
    if (tid < MLP_H)     b1s[tid] = b1[tid];
    __syncthreads();

    int wid = tid >> 5;
    int slot = wid >> 1;
    int p = wid & 1;
    int n = blockIdx.x * 4 + slot;
    int j = tid & 31;
    float wa = w1s[j], wb = w1s[MLP_H + j], bb = b1s[j];

    float s0 = 0.f, s1 = 0.f, s2 = 0.f, s3 = 0.f, s4 = 0.f, xs = 0.f;
    if (n < NN) {
        int k0 = g_off[n], k1 = g_off[n + 1];
        int deg = k1 - k0;
        int half = (deg + 1) >> 1;
        int a0 = k0 + p * half;
        int a1 = a0 + half; if (a1 > k1) a1 = k1;
        int k = a0;
        for (; k + 2 <= a1; k += 2) {
            int sa = __ldg(&g_esrc[k]);
            int sb = __ldg(&g_esrc[k + 1]);
            float2 ea0 = __ldg(&g_eea[k]);
            float2 ea1 = __ldg(&g_eea[k + 1]);
            float4 xa0 = __ldg(&g_x8[2 * sa]);
            float4 xb0 = __ldg(&g_x8[2 * sa + 1]);
            float4 xa1 = __ldg(&g_x8[2 * sb]);
            float4 xb1 = __ldg(&g_x8[2 * sb + 1]);
            float h0 = fmaxf(fmaf(ea0.x, wa, fmaf(ea0.y, wb, bb)), 0.f);
            float h1 = fmaxf(fmaf(ea1.x, wa, fmaf(ea1.y, wb, bb)), 0.f);
            s0 = fmaf(h0, xa0.x, s0); s1 = fmaf(h0, xa0.y, s1); s2 = fmaf(h0, xa0.z, s2);
            s3 = fmaf(h0, xa0.w, s3); s4 = fmaf(h0, xb0.x, s4);
            s0 = fmaf(h1, xa1.x, s0); s1 = fmaf(h1, xa1.y, s1); s2 = fmaf(h1, xa1.z, s2);
            s3 = fmaf(h1, xa1.w, s3); s4 = fmaf(h1, xb1.x, s4);
            if (j < FINN) {
                float v0 = (j == 0) ? xa0.x : (j == 1) ? xa0.y : (j == 2) ? xa0.z : (j == 3) ? xa0.w : xb0.x;
                float v1 = (j == 0) ? xa1.x : (j == 1) ? xa1.y : (j == 2) ? xa1.z : (j == 3) ? xa1.w : xb1.x;
                xs += v0 + v1;
            }
        }
        if (k < a1) {
            int sa = __ldg(&g_esrc[k]);
            float2 ea0 = __ldg(&g_eea[k]);
            float4 xa0 = __ldg(&g_x8[2 * sa]);
            float4 xb0 = __ldg(&g_x8[2 * sa + 1]);
            float h0 = fmaxf(fmaf(ea0.x, wa, fmaf(ea0.y, wb, bb)), 0.f);
            s0 = fmaf(h0, xa0.x, s0); s1 = fmaf(h0, xa0.y, s1); s2 = fmaf(h0, xa0.z, s2);
            s3 = fmaf(h0, xa0.w, s3); s4 = fmaf(h0, xb0.x, s4);
            if (j < FINN) {
                float v0 = (j == 0) ? xa0.x : (j == 1) ? xa0.y : (j == 2) ? xa0.z : (j == 3) ? xa0.w : xb0.x;
                xs += v0;
            }
        }
    }

    if (p == 0) {
        float* pp = part[slot] + j * 5;
        pp[0] = s0; pp[1] = s1; pp[2] = s2; pp[3] = s3; pp[4] = s4;
        if (j < FINN) part[slot][160 + j] = xs;
    }
    __syncthreads();
    if (p == 1 && n < NN) {
        const float* pp = part[slot] + j * 5;
        float* Sp = g_S + n * SDIM + j * 5;
        Sp[0] = s0 + pp[0]; Sp[1] = s1 + pp[1]; Sp[2] = s2 + pp[2];
        Sp[3] = s3 + pp[3]; Sp[4] = s4 + pp[4];
        if (j < FINN) g_S[n * SDIM + 160 + j] = xs + part[slot][160 + j];
    }
}

// ---------------- fused: x1 = relu(NNConv), xl = x1@gat_w, a_src/a_dst ----------------
__global__ void k_x1xl(const float* __restrict__ x, const float* __restrict__ w2,
                       const float* __restrict__ b2, const float* __restrict__ root,
                       const float* __restrict__ nbias, const float* __restrict__ gw,
                       const float* __restrict__ asv, const float* __restrict__ adv) {
    __shared__ float x1s[8][64];
    int w = threadIdx.x >> 5, lane = threadIdx.x & 31;
    int n = blockIdx.x * 8 + w;
    if (n >= NN) return;
    const float* Sp = g_S + n * SDIM;
    int o0 = lane, o1 = lane + 32;

    float acc0 = __ldg(&nbias[o0]);
    float acc1 = __ldg(&nbias[o1]);
    const float* xp = x + n * FINN;
#pragma unroll
    for (int i = 0; i < FINN; i++) {
        float xi = __ldg(xp + i);
        acc0 = fmaf(xi, __ldg(&root[i * FOUT + o0]), acc0);
        acc1 = fmaf(xi, __ldg(&root[i * FOUT + o1]), acc1);
    }
#pragma unroll 4
    for (int j = 0; j < MLP_H; j++) {
#pragma unroll
        for (int i = 0; i < FINN; i++) {
            float sv = Sp[j * 5 + i];
            acc0 = fmaf(sv, __ldg(&w2[j * 320 + i * 64 + o0]), acc0);
            acc1 = fmaf(sv, __ldg(&w2[j * 320 + i * 64 + o1]), acc1);
        }
    }
#pragma unroll
    for (int i = 0; i < FINN; i++) {
        float sv = Sp[160 + i];
        acc0 = fmaf(sv, __ldg(&b2[i * 64 + o0]), acc0);
        acc1 = fmaf(sv, __ldg(&b2[i * 64 + o1]), acc1);
    }
    x1s[w][o0] = fmaxf(acc0, 0.f);
    x1s[w][o1] = fmaxf(acc1, 0.f);
    __syncwarp();

    int c = lane;
    float acc = 0.f;
    if (c < CC) {
#pragma unroll 8
        for (int o = 0; o < FOUT; o++)
            acc = fmaf(x1s[w][o], __ldg(&gw[o * CC + c]), acc);
        g_xl[n * CC + c] = acc;
    }
    float vs = (c < CC) ? acc * __ldg(&asv[c]) : 0.f;
    float vd = (c < CC) ? acc * __ldg(&adv[c]) : 0.f;
    for (int s = 16; s; s >>= 1) {
        vs += __shfl_xor_sync(0xffffffffu, vs, s);
        vd += __shfl_xor_sync(0xffffffffu, vd, s);
    }
    if (lane == 0) { g_asrc[n] = vs; g_adst[n] = vd; }
}

__device__ __forceinline__ float lrelu(float a) { return a > 0.f ? a : 0.2f * a; }

// ---------------- FUSED GAT + fc1 ----------------
// Phase 1 (per warp = one node): online-softmax GAT -> relu -> compact
// nonzero outputs into block-local smem (<=216 entries).
// Phase 2 (whole block): stream fc1 weight rows for this block's entries
// (explicit 8-row batch) and atomically accumulate into g_hid.
// GAT compute of late blocks overlaps fc1 DRAM traffic of early blocks.
__global__ void k_gatfc1(const float* __restrict__ gbias, const float* __restrict__ w) {
    __shared__ float sval[216];
    __shared__ int   srow[216];
    __shared__ int   scnt;
    int tid = threadIdx.x;
    if (tid == 0) scnt = 0;
    __syncthreads();

    int n = blockIdx.x * 8 + (tid >> 5);      // grid 1250*8 == NN exactly
    int lane = tid & 31;
    int k0 = g_off[n], k1 = g_off[n + 1];
    int deg = k1 - k0;
    float ad = g_adst[n];
    float aself = lrelu(g_asrc[n] + ad);

    float sa[MAXL]; int ss[MAXL];
    int nl = 0;
    float m = -1e30f, d = 0.f;
    for (int k = k0 + lane; k < k1; k += 32) {
        int s = __ldg(&g_esrc[k]);
        float a = lrelu(__ldg(&g_asrc[s]) + ad);
        if (nl < MAXL) { sa[nl] = a; ss[nl] = s; }
        nl++;
        float mn = fmaxf(m, a);
        d = fmaf(d, __expf(m - mn), __expf(a - mn));
        m = mn;
    }
    for (int s = 16; s; s >>= 1) {
        float m2 = __shfl_xor_sync(0xffffffffu, m, s);
        float d2 = __shfl_xor_sync(0xffffffffu, d, s);
        float mn = fmaxf(m, m2);
        d = fmaf(d, __expf(m - mn), d2 * __expf(m2 - mn));
        m = mn;
    }
    {
        float mn = fmaxf(m, aself);
        d = fmaf(d, __expf(m - mn), __expf(aself - mn));
        m = mn;
    }
    float inv = 1.f / d;

    int c = lane;
    float out = (c < CC) ? __expf(aself - m) * inv * g_xl[n * CC + c] : 0.f;

    if (deg <= 32 * MAXL) {
        int nb = (deg + 31) >> 5;
        for (int q = 0; q < nb; q++) {
            float wq = (q < nl) ? __expf(sa[q] - m) * inv : 0.f;
            int sq = (q < nl) ? ss[q] : 0;
            int cnt = min(32, deg - (q << 5));
            for (int i = 0; i < cnt; i++) {
                float wi = __shfl_sync(0xffffffffu, wq, i);
                int si = __shfl_sync(0xffffffffu, sq, i);
                if (c < CC) out = fmaf(wi, __ldg(&g_xl[si * CC + c]), out);
            }
        }
    } else {
        for (int k = k0; k < k1; k++) {
            int s2 = __ldg(&g_esrc[k]);
            float wv = __expf(lrelu(__ldg(&g_asrc[s2]) + ad) - m) * inv;
            if (c < CC) out = fmaf(wv, __ldg(&g_xl[s2 * CC + c]), out);
        }
    }

    // compaction into block-local smem
    float r = 0.f;
    bool pred = false;
    if (c < CC) {
        r = out + __ldg(&gbias[c]);
        pred = (r > 0.f);
    }
    unsigned mask = __ballot_sync(0xffffffffu, pred);
    int wcnt = __popc(mask);
    if (wcnt) {
        int leader = __ffs(mask) - 1;
        int base = 0;
        if (lane == leader) base = atomicAdd(&scnt, wcnt);
        base = __shfl_sync(0xffffffffu, base, leader);
        if (pred) {
            int off = __popc(mask & ((1u << lane) - 1));
            srow[base + off] = n * CC + c;
            sval[base + off] = r;
        }
    }
    __syncthreads();

    // Phase 2: fc1 for this block's entries
    int cnt = scnt;
    int t = tid;
    float a0 = 0.f, a1 = 0.f;
    int i = 0;
    for (; i + 8 <= cnt; i += 8) {
        int r0 = srow[i],     r1 = srow[i + 1];
        int r2 = srow[i + 2], r3 = srow[i + 3];
        int r4 = srow[i + 4], r5 = srow[i + 5];
        int r6 = srow[i + 6], r7 = srow[i + 7];
        float v0 = sval[i],     v1 = sval[i + 1];
        float v2 = sval[i + 2], v3 = sval[i + 3];
        float v4 = sval[i + 4], v5 = sval[i + 5];
        float v6 = sval[i + 6], v7 = sval[i + 7];
        const float* p0 = w + (size_t)r0 * HIDD;
        const float* p1 = w + (size_t)r1 * HIDD;
        const float* p2 = w + (size_t)r2 * HIDD;
        const float* p3 = w + (size_t)r3 * HIDD;
        const float* p4 = w + (size_t)r4 * HIDD;
        const float* p5 = w + (size_t)r5 * HIDD;
        const float* p6 = w + (size_t)r6 * HIDD;
        const float* p7 = w + (size_t)r7 * HIDD;
        a0 = fmaf(v0, __ldg(p0 + t), a0);
        a0 = fmaf(v1, __ldg(p1 + t), a0);
        a0 = fmaf(v2, __ldg(p2 + t), a0);
        a0 = fmaf(v3, __ldg(p3 + t), a0);
        a0 = fmaf(v4, __ldg(p4 + t), a0);
        a0 = fmaf(v5, __ldg(p5 + t), a0);
        a0 = fmaf(v6, __ldg(p6 + t), a0);
        a0 = fmaf(v7, __ldg(p7 + t), a0);
        if (t < HIDD - 256) {
            a1 = fmaf(v0, __ldg(p0 + 256 + t), a1);
            a1 = fmaf(v1, __ldg(p1 + 256 + t), a1);
            a1 = fmaf(v2, __ldg(p2 + 256 + t), a1);
            a1 = fmaf(v3, __ldg(p3 + 256 + t), a1);
            a1 = fmaf(v4, __ldg(p4 + 256 + t), a1);
            a1 = fmaf(v5, __ldg(p5 + 256 + t), a1);
            a1 = fmaf(v6, __ldg(p6 + 256 + t), a1);
            a1 = fmaf(v7, __ldg(p7 + 256 + t), a1);
        }
    }
    for (; i < cnt; i++) {
        int rr = srow[i];
        float v = sval[i];
        const float* p = w + (size_t)rr * HIDD;
        a0 = fmaf(v, __ldg(p + t), a0);
        if (t < HIDD - 256) a1 = fmaf(v, __ldg(p + 256 + t), a1);
    }
    if (cnt) {
        atomicAdd(&g_hid[t], a0);
        if (t < HIDD - 256) atomicAdd(&g_hid[256 + t], a1);
    }
}

// ---------------- fc2: 30 blocks x 15 rows, atomic partials; self-cleans g_hid ----------------
__global__ void k_fc2(const float* __restrict__ b1v, const float* __restrict__ w2) {
    __shared__ float hs[15];
    int b = blockIdx.x;
    int t = threadIdx.x;
    if (t < 15) {
        int h = b * 15 + t;
        float hv = g_hid[h] + __ldg(&b1v[h]);
        hs[t] = hv > 0.f ? hv : 0.f;
    }
    __syncthreads();
    float acc = 0.f;
#pragma unroll
    for (int i = 0; i < 15; i++) {
        int h = b * 15 + i;
        acc = fmaf(hs[i], __ldg(&w2[h * FINAL + t]), acc);
    }
    atomicAdd(&g_fin[t], acc);
    if (t < 15) g_hid[b * 15 + t] = 0.f;
}

// ---------------- out: final relu; self-cleans g_fin ----------------
__global__ void k_out(const float* __restrict__ b2v, float* __restrict__ out) {
    int t = threadIdx.x;
    float v = g_fin[t] + __ldg(&b2v[t]);
    g_fin[t] = 0.f;
    out[t] = v > 0.f ? v : 0.f;
}

// ---------------- launcher ----------------
extern "C" void kernel_launch(void* const* d_in, const int* in_sizes, int n_in,
                              void* d_out, int out_size) {
    const float* x        = (const float*)d_in[0];
    const int*   ei       = (const int*)  d_in[1];
    const float* ea       = (const float*)d_in[2];
    const float* mlp_w1   = (const float*)d_in[3];
    const float* mlp_b1   = (const float*)d_in[4];
    const float* mlp_w2   = (const float*)d_in[5];
    const float* mlp_b2   = (const float*)d_in[6];
    const float* nn_root  = (const float*)d_in[7];
    const float* nn_bias  = (const float*)d_in[8];
    const float* gat_w    = (const float*)d_in[9];
    const float* att_src  = (const float*)d_in[10];
    const float* att_dst  = (const float*)d_in[11];
    const float* gat_bias = (const float*)d_in[12];
    const float* fc1_w    = (const float*)d_in[13];
    const float* fc1_b    = (const float*)d_in[14];
    const float* fc2_w    = (const float*)d_in[15];
    const float* fc2_b    = (const float*)d_in[16];
    float* out = (float*)d_out;

    k_hist<<<(EE + 255) / 256, 256>>>(ei, x);
    k_scan<<<1, 256>>>();
    k_scatter<<<(EE + 255) / 256, 256>>>(ei, ea);
    k_S<<<(NN + 3) / 4, 256>>>(mlp_w1, mlp_b1);
    k_x1xl<<<(NN + 7) / 8, 256>>>(x, mlp_w2, mlp_b2, nn_root, nn_bias,
                                  gat_w, att_src, att_dst);
    k_gatfc1<<<NN / 8, 256>>>(gat_bias, fc1_w);
    k_fc2<<<30, 128>>>(fc1_b, fc2_w);
    k_out<<<1, 128>>>(fc2_b, out);
}

// round 17
// speedup vs baseline: 1.1886x; 1.0726x over previous
#include <cuda_runtime.h>

#define NN     10000
#define EE     320000
#define FINN   5
#define FOUT   64
#define MLPH   32
#define CC     27
#define HIDD   450
#define FINAL  128
#define MLP_H  32
#define MAXL   8            // max edges per lane in GAT reg cache (deg <= 256)

// ---------------- scratch (no allocations allowed) ----------------
// Self-cleaning invariant: zero-state restored by the last consumer.
static __device__ int    g_deg[NN];        // zeroed by k_scan
static __device__ int    g_off[NN + 1];
static __device__ int    g_rank[EE];
static __device__ int    g_esrc[EE];       // dst-sorted source ids
static __device__ float2 g_eea[EE];        // dst-sorted edge attrs
static __device__ float4 g_x8[2 * NN];     // x padded to 8 floats (2x float4)
static __device__ float  g_xl[NN * CC];
static __device__ float  g_asrc[NN];
static __device__ float  g_adst[NN];
static __device__ float  g_hid[HIDD];      // zeroed by k_fc2
static __device__ float  g_fin[FINAL];     // zeroed by k_out

// ---------------- hist (+ x padding piggybacked on first NN threads) ----------------
__global__ void k_hist(const int* __restrict__ ei, const float* __restrict__ x) {
    int e = blockIdx.x * blockDim.x + threadIdx.x;
    if (e < NN) {
        const float* xp = x + e * FINN;
        g_x8[2 * e]     = make_float4(__ldg(xp), __ldg(xp + 1), __ldg(xp + 2), __ldg(xp + 3));
        g_x8[2 * e + 1] = make_float4(__ldg(xp + 4), 0.f, 0.f, 0.f);
    }
    if (e < EE) g_rank[e] = atomicAdd(&g_deg[ei[EE + e]], 1);
}

// scan via smem: coalesced global in/out; self-cleans g_deg
__global__ void k_scan() {
    __shared__ int sdeg[10240];
    __shared__ int wsum[8];
    __shared__ int woff[8];
    int tid = threadIdx.x;
    for (int i = tid; i < 10240; i += 256) sdeg[i] = (i < NN) ? g_deg[i] : 0;
    __syncthreads();
    int start = tid * 40;
    int local = 0;
#pragma unroll 8
    for (int i = 0; i < 40; i++) local += sdeg[start + i];
    int lane = tid & 31, w = tid >> 5;
    int incl = local;
    for (int s = 1; s < 32; s <<= 1) {
        int t = __shfl_up_sync(0xffffffffu, incl, s);
        if (lane >= s) incl += t;
    }
    if (lane == 31) wsum[w] = incl;
    __syncthreads();
    if (tid == 0) {
        int c = 0;
        for (int i = 0; i < 8; i++) { woff[i] = c; c += wsum[i]; }
    }
    __syncthreads();
    int run = incl - local + woff[w];
#pragma unroll 8
    for (int i = 0; i < 40; i++) {
        int t = sdeg[start + i];
        sdeg[start + i] = run;
        run += t;
    }
    __syncthreads();
    for (int i = tid; i < NN; i += 256) {
        g_off[i] = sdeg[i];
        g_deg[i] = 0;
    }
    if (tid == 0) g_off[NN] = EE;
}

// atomic-free scatter: dst-sorted (src, edge_attr) streams (12 B/edge)
__global__ void k_scatter(const int* __restrict__ ei, const float* __restrict__ ea) {
    int e = blockIdx.x * blockDim.x + threadIdx.x;
    if (e >= EE) return;
    int dst = __ldg(&ei[EE + e]);
    int slot = g_off[dst] + g_rank[e];
    g_esrc[slot] = __ldg(&ei[e]);
    g_eea[slot] = __ldg((const float2*)ea + e);
}

// ---------------- FUSED S-build + NNConv epilogue + GAT linear ----------------
// Phase 1: two warps per node accumulate S halves; combined into smem.
// Phase 2: same warp pair computes x1 = relu(NNConv) (warp p owns outputs
// lane+32p), then warp p=0 computes xl = x1@gat_w and a_src/a_dst.
// No g_S global round-trip; x1 phase of early blocks overlaps S phase of late.
__global__ void k_Sx1(const float* __restrict__ w1, const float* __restrict__ b1,
                      const float* __restrict__ x, const float* __restrict__ w2,
                      const float* __restrict__ b2, const float* __restrict__ root,
                      const float* __restrict__ nbias, const float* __restrict__ gw,
                      const float* __restrict__ asv, const float* __restrict__ adv) {
    __shared__ float w1s[2 * MLP_H];
    __shared__ float b1s[MLP_H];
    __shared__ float part[4][168];         // p=0 partials
    __shared__ float sS[4][168];           // combined S rows
    __shared__ float x1s[4][FOUT];
    int tid = threadIdx.x;
    if (tid < 2 * MLP_H) w1s[tid] = w1[tid];
    if (tid < MLP_H)     b1s[tid] = b1[tid];
    __syncthreads();

    int wid = tid >> 5;
    int slot = wid >> 1;                   // 0..3: node within block
    int p = wid & 1;                       // warp parity within pair
    int n = blockIdx.x * 4 + slot;         // grid 2500*4 == NN exactly
    int j = tid & 31;
    float wa = w1s[j], wb = w1s[MLP_H + j], bb = b1s[j];

    // ---- Phase 1: S accumulation over this warp's half of the edges ----
    float s0 = 0.f, s1 = 0.f, s2 = 0.f, s3 = 0.f, s4 = 0.f, xs = 0.f;
    {
        int k0 = g_off[n], k1 = g_off[n + 1];
        int deg = k1 - k0;
        int half = (deg + 1) >> 1;
        int a0 = k0 + p * half;
        int a1 = a0 + half; if (a1 > k1) a1 = k1;
        int k = a0;
        for (; k + 2 <= a1; k += 2) {
            int sa = __ldg(&g_esrc[k]);
            int sb = __ldg(&g_esrc[k + 1]);
            float2 ea0 = __ldg(&g_eea[k]);
            float2 ea1 = __ldg(&g_eea[k + 1]);
            float4 xa0 = __ldg(&g_x8[2 * sa]);
            float4 xb0 = __ldg(&g_x8[2 * sa + 1]);
            float4 xa1 = __ldg(&g_x8[2 * sb]);
            float4 xb1 = __ldg(&g_x8[2 * sb + 1]);
            float h0 = fmaxf(fmaf(ea0.x, wa, fmaf(ea0.y, wb, bb)), 0.f);
            float h1 = fmaxf(fmaf(ea1.x, wa, fmaf(ea1.y, wb, bb)), 0.f);
            s0 = fmaf(h0, xa0.x, s0); s1 = fmaf(h0, xa0.y, s1); s2 = fmaf(h0, xa0.z, s2);
            s3 = fmaf(h0, xa0.w, s3); s4 = fmaf(h0, xb0.x, s4);
            s0 = fmaf(h1, xa1.x, s0); s1 = fmaf(h1, xa1.y, s1); s2 = fmaf(h1, xa1.z, s2);
            s3 = fmaf(h1, xa1.w, s3); s4 = fmaf(h1, xb1.x, s4);
            if (j < FINN) {
                float v0 = (j == 0) ? xa0.x : (j == 1) ? xa0.y : (j == 2) ? xa0.z : (j == 3) ? xa0.w : xb0.x;
                float v1 = (j == 0) ? xa1.x : (j == 1) ? xa1.y : (j == 2) ? xa1.z : (j == 3) ? xa1.w : xb1.x;
                xs += v0 + v1;
            }
        }
        if (k < a1) {
            int sa = __ldg(&g_esrc[k]);
            float2 ea0 = __ldg(&g_eea[k]);
            float4 xa0 = __ldg(&g_x8[2 * sa]);
            float4 xb0 = __ldg(&g_x8[2 * sa + 1]);
            float h0 = fmaxf(fmaf(ea0.x, wa, fmaf(ea0.y, wb, bb)), 0.f);
            s0 = fmaf(h0, xa0.x, s0); s1 = fmaf(h0, xa0.y, s1); s2 = fmaf(h0, xa0.z, s2);
            s3 = fmaf(h0, xa0.w, s3); s4 = fmaf(h0, xb0.x, s4);
            if (j < FINN) {
                float v0 = (j == 0) ? xa0.x : (j == 1) ? xa0.y : (j == 2) ? xa0.z : (j == 3) ? xa0.w : xb0.x;
                xs += v0;
            }
        }
    }
    if (p == 0) {
        float* pp = part[slot] + j * 5;
        pp[0] = s0; pp[1] = s1; pp[2] = s2; pp[3] = s3; pp[4] = s4;
        if (j < FINN) part[slot][160 + j] = xs;
    }
    __syncthreads();
    if (p == 1) {
        const float* pp = part[slot] + j * 5;
        float* Sp = sS[slot] + j * 5;
        Sp[0] = s0 + pp[0]; Sp[1] = s1 + pp[1]; Sp[2] = s2 + pp[2];
        Sp[3] = s3 + pp[3]; Sp[4] = s4 + pp[4];
        if (j < FINN) sS[slot][160 + j] = xs + part[slot][160 + j];
    }
    __syncthreads();

    // ---- Phase 2: x1 = relu(S@W2' + Xsum@b2' + x@root + nn_bias) ----
    {
        int lane = j;
        int o = lane + p * 32;
        const float* Sp = sS[slot];
        float acc = __ldg(&nbias[o]);
        const float* xp = x + n * FINN;
#pragma unroll
        for (int i = 0; i < FINN; i++)
            acc = fmaf(__ldg(xp + i), __ldg(&root[i * FOUT + o]), acc);
#pragma unroll 4
        for (int jj = 0; jj < MLP_H; jj++) {
#pragma unroll
            for (int i = 0; i < FINN; i++)
                acc = fmaf(Sp[jj * 5 + i], __ldg(&w2[jj * 320 + i * 64 + o]), acc);
        }
#pragma unroll
        for (int i = 0; i < FINN; i++)
            acc = fmaf(Sp[160 + i], __ldg(&b2[i * 64 + o]), acc);
        x1s[slot][o] = fmaxf(acc, 0.f);
    }
    __syncthreads();

    // ---- xl = x1 @ gat_w ; a_src/a_dst (warp p=0 of each pair) ----
    if (p == 0) {
        int c = j;
        float acc = 0.f;
        if (c < CC) {
#pragma unroll 8
            for (int o = 0; o < FOUT; o++)
                acc = fmaf(x1s[slot][o], __ldg(&gw[o * CC + c]), acc);
            g_xl[n * CC + c] = acc;
        }
        float vs = (c < CC) ? acc * __ldg(&asv[c]) : 0.f;
        float vd = (c < CC) ? acc * __ldg(&adv[c]) : 0.f;
        for (int s = 16; s; s >>= 1) {
            vs += __shfl_xor_sync(0xffffffffu, vs, s);
            vd += __shfl_xor_sync(0xffffffffu, vd, s);
        }
        if (j == 0) { g_asrc[n] = vs; g_adst[n] = vd; }
    }
}

__device__ __forceinline__ float lrelu(float a) { return a > 0.f ? a : 0.2f * a; }

// ---------------- FUSED GAT + fc1 ----------------
__global__ void k_gatfc1(const float* __restrict__ gbias, const float* __restrict__ w) {
    __shared__ float sval[216];
    __shared__ int   srow[216];
    __shared__ int   scnt;
    int tid = threadIdx.x;
    if (tid == 0) scnt = 0;
    __syncthreads();

    int n = blockIdx.x * 8 + (tid >> 5);      // grid 1250*8 == NN exactly
    int lane = tid & 31;
    int k0 = g_off[n], k1 = g_off[n + 1];
    int deg = k1 - k0;
    float ad = g_adst[n];
    float aself = lrelu(g_asrc[n] + ad);

    float sa[MAXL]; int ss[MAXL];
    int nl = 0;
    float m = -1e30f, d = 0.f;
    for (int k = k0 + lane; k < k1; k += 32) {
        int s = __ldg(&g_esrc[k]);
        float a = lrelu(__ldg(&g_asrc[s]) + ad);
        if (nl < MAXL) { sa[nl] = a; ss[nl] = s; }
        nl++;
        float mn = fmaxf(m, a);
        d = fmaf(d, __expf(m - mn), __expf(a - mn));
        m = mn;
    }
    for (int s = 16; s; s >>= 1) {
        float m2 = __shfl_xor_sync(0xffffffffu, m, s);
        float d2 = __shfl_xor_sync(0xffffffffu, d, s);
        float mn = fmaxf(m, m2);
        d = fmaf(d, __expf(m - mn), d2 * __expf(m2 - mn));
        m = mn;
    }
    {
        float mn = fmaxf(m, aself);
        d = fmaf(d, __expf(m - mn), __expf(aself - mn));
        m = mn;
    }
    float inv = 1.f / d;

    int c = lane;
    float out = (c < CC) ? __expf(aself - m) * inv * g_xl[n * CC + c] : 0.f;

    if (deg <= 32 * MAXL) {
        int nb = (deg + 31) >> 5;
        for (int q = 0; q < nb; q++) {
            float wq = (q < nl) ? __expf(sa[q] - m) * inv : 0.f;
            int sq = (q < nl) ? ss[q] : 0;
            int cnt = min(32, deg - (q << 5));
            for (int i = 0; i < cnt; i++) {
                float wi = __shfl_sync(0xffffffffu, wq, i);
                int si = __shfl_sync(0xffffffffu, sq, i);
                if (c < CC) out = fmaf(wi, __ldg(&g_xl[si * CC + c]), out);
            }
        }
    } else {
        for (int k = k0; k < k1; k++) {
            int s2 = __ldg(&g_esrc[k]);
            float wv = __expf(lrelu(__ldg(&g_asrc[s2]) + ad) - m) * inv;
            if (c < CC) out = fmaf(wv, __ldg(&g_xl[s2 * CC + c]), out);
        }
    }

    // compaction into block-local smem
    float r = 0.f;
    bool pred = false;
    if (c < CC) {
        r = out + __ldg(&gbias[c]);
        pred = (r > 0.f);
    }
    unsigned mask = __ballot_sync(0xffffffffu, pred);
    int wcnt = __popc(mask);
    if (wcnt) {
        int leader = __ffs(mask) - 1;
        int base = 0;
        if (lane == leader) base = atomicAdd(&scnt, wcnt);
        base = __shfl_sync(0xffffffffu, base, leader);
        if (pred) {
            int off = __popc(mask & ((1u << lane) - 1));
            srow[base + off] = n * CC + c;
            sval[base + off] = r;
        }
    }
    __syncthreads();

    // Phase 2: fc1 for this block's entries
    int cnt = scnt;
    int t = tid;
    float a0 = 0.f, a1 = 0.f;
    int i = 0;
    for (; i + 8 <= cnt; i += 8) {
        int r0 = srow[i],     r1 = srow[i + 1];
        int r2 = srow[i + 2], r3 = srow[i + 3];
        int r4 = srow[i + 4], r5 = srow[i + 5];
        int r6 = srow[i + 6], r7 = srow[i + 7];
        float v0 = sval[i],     v1 = sval[i + 1];
        float v2 = sval[i + 2], v3 = sval[i + 3];
        float v4 = sval[i + 4], v5 = sval[i + 5];
        float v6 = sval[i + 6], v7 = sval[i + 7];
        const float* p0 = w + (size_t)r0 * HIDD;
        const float* p1 = w + (size_t)r1 * HIDD;
        const float* p2 = w + (size_t)r2 * HIDD;
        const float* p3 = w + (size_t)r3 * HIDD;
        const float* p4 = w + (size_t)r4 * HIDD;
        const float* p5 = w + (size_t)r5 * HIDD;
        const float* p6 = w + (size_t)r6 * HIDD;
        const float* p7 = w + (size_t)r7 * HIDD;
        a0 = fmaf(v0, __ldg(p0 + t), a0);
        a0 = fmaf(v1, __ldg(p1 + t), a0);
        a0 = fmaf(v2, __ldg(p2 + t), a0);
        a0 = fmaf(v3, __ldg(p3 + t), a0);
        a0 = fmaf(v4, __ldg(p4 + t), a0);
        a0 = fmaf(v5, __ldg(p5 + t), a0);
        a0 = fmaf(v6, __ldg(p6 + t), a0);
        a0 = fmaf(v7, __ldg(p7 + t), a0);
        if (t < HIDD - 256) {
            a1 = fmaf(v0, __ldg(p0 + 256 + t), a1);
            a1 = fmaf(v1, __ldg(p1 + 256 + t), a1);
            a1 = fmaf(v2, __ldg(p2 + 256 + t), a1);
            a1 = fmaf(v3, __ldg(p3 + 256 + t), a1);
            a1 = fmaf(v4, __ldg(p4 + 256 + t), a1);
            a1 = fmaf(v5, __ldg(p5 + 256 + t), a1);
            a1 = fmaf(v6, __ldg(p6 + 256 + t), a1);
            a1 = fmaf(v7, __ldg(p7 + 256 + t), a1);
        }
    }
    for (; i < cnt; i++) {
        int rr = srow[i];
        float v = sval[i];
        const float* p = w + (size_t)rr * HIDD;
        a0 = fmaf(v, __ldg(p + t), a0);
        if (t < HIDD - 256) a1 = fmaf(v, __ldg(p + 256 + t), a1);
    }
    if (cnt) {
        atomicAdd(&g_hid[t], a0);
        if (t < HIDD - 256) atomicAdd(&g_hid[256 + t], a1);
    }
}

// ---------------- fc2: 30 blocks x 15 rows, atomic partials; self-cleans g_hid ----------------
__global__ void k_fc2(const float* __restrict__ b1v, const float* __restrict__ w2) {
    __shared__ float hs[15];
    int b = blockIdx.x;
    int t = threadIdx.x;
    if (t < 15) {
        int h = b * 15 + t;
        float hv = g_hid[h] + __ldg(&b1v[h]);
        hs[t] = hv > 0.f ? hv : 0.f;
    }
    __syncthreads();
    float acc = 0.f;
#pragma unroll
    for (int i = 0; i < 15; i++) {
        int h = b * 15 + i;
        acc = fmaf(hs[i], __ldg(&w2[h * FINAL + t]), acc);
    }
    atomicAdd(&g_fin[t], acc);
    if (t < 15) g_hid[b * 15 + t] = 0.f;
}

// ---------------- out: final relu; self-cleans g_fin ----------------
__global__ void k_out(const float* __restrict__ b2v, float* __restrict__ out) {
    int t = threadIdx.x;
    float v = g_fin[t] + __ldg(&b2v[t]);
    g_fin[t] = 0.f;
    out[t] = v > 0.f ? v : 0.f;
}

// ---------------- launcher ----------------
extern "C" void kernel_launch(void* const* d_in, const int* in_sizes, int n_in,
                              void* d_out, int out_size) {
    const float* x        = (const float*)d_in[0];
    const int*   ei       = (const int*)  d_in[1];
    const float* ea       = (const float*)d_in[2];
    const float* mlp_w1   = (const float*)d_in[3];
    const float* mlp_b1   = (const float*)d_in[4];
    const float* mlp_w2   = (const float*)d_in[5];
    const float* mlp_b2   = (const float*)d_in[6];
    const float* nn_root  = (const float*)d_in[7];
    const float* nn_bias  = (const float*)d_in[8];
    const float* gat_w    = (const float*)d_in[9];
    const float* att_src  = (const float*)d_in[10];
    const float* att_dst  = (const float*)d_in[11];
    const float* gat_bias = (const float*)d_in[12];
    const float* fc1_w    = (const float*)d_in[13];
    const float* fc1_b    = (const float*)d_in[14];
    const float* fc2_w    = (const float*)d_in[15];
    const float* fc2_b    = (const float*)d_in[16];
    float* out = (float*)d_out;

    k_hist<<<(EE + 255) / 256, 256>>>(ei, x);
    k_scan<<<1, 256>>>();
    k_scatter<<<(EE + 255) / 256, 256>>>(ei, ea);
    k_Sx1<<<NN / 4, 256>>>(mlp_w1, mlp_b1, x, mlp_w2, mlp_b2, nn_root,
                           nn_bias, gat_w, att_src, att_dst);
    k_gatfc1<<<NN / 8, 256>>>(gat_bias, fc1_w);
    k_fc2<<<30, 128>>>(fc1_b, fc2_w);
    k_out<<<1, 128>>>(fc2_b, out);
}